// round 1
// baseline (speedup 1.0000x reference)
#include <cuda_runtime.h>
#include <math.h>

// Problem constants (fixed by setup_inputs)
#define BB 4
#define PP 900
#define DD 512
#define HH 8
#define DK 64
#define NBH 32          // B*H
#define SIDE 30
#define C1 32           // conv1 out channels (4*h)

// ---------------- scratch (device globals; allocated at module load) ----------------
__device__ float g_q[BB*PP*DD];                   // [3600][512]
__device__ float g_k[BB*PP*DD];                   // [3600][512]
__device__ float g_scores[(size_t)NBH*PP*PP];     // [32][900][900]  (becomes attn in place)
__device__ int   g_idx[NBH*PP];                   // [32][900] column argmax
__device__ float g_conv1[(size_t)BB*C1*PP*PP];    // [4][32][900][900]
__device__ float g_part[BB*PP*15];                // [4][900][15] partial dot-products

// =====================================================================
// 1) Projection GEMM: C[m][n] = sum_k A[m][k] * W[n][k] + bias[n]
//    M=3600, N=512, K=512.  which==0 -> g_q, which==1 -> g_k
// =====================================================================
__global__ void proj_kernel(const float* __restrict__ A,
                            const float* __restrict__ W,
                            const float* __restrict__ bias,
                            int which)
{
    __shared__ float As[16][64];
    __shared__ float Bs[16][64];
    float* C = which ? g_k : g_q;

    int tid = threadIdx.x;
    int m0 = blockIdx.x * 64;
    int n0 = blockIdx.y * 64;
    int tx = tid & 15, ty = tid >> 4;

    float acc[4][4] = {};
    for (int k0 = 0; k0 < 512; k0 += 16) {
        #pragma unroll
        for (int i = 0; i < 4; i++) {
            int idx = tid + i * 256;
            int r = idx >> 4, kk = idx & 15;
            int m = m0 + r;
            As[kk][r] = (m < 3600) ? A[(size_t)m * 512 + k0 + kk] : 0.f;
            Bs[kk][r] = W[(size_t)(n0 + r) * 512 + k0 + kk];
        }
        __syncthreads();
        #pragma unroll
        for (int kk = 0; kk < 16; kk++) {
            float a[4], b[4];
            #pragma unroll
            for (int i = 0; i < 4; i++) a[i] = As[kk][ty * 4 + i];
            #pragma unroll
            for (int j = 0; j < 4; j++) b[j] = Bs[kk][tx * 4 + j];
            #pragma unroll
            for (int i = 0; i < 4; i++)
                #pragma unroll
                for (int j = 0; j < 4; j++)
                    acc[i][j] += a[i] * b[j];
        }
        __syncthreads();
    }
    #pragma unroll
    for (int i = 0; i < 4; i++) {
        int m = m0 + ty * 4 + i;
        if (m >= 3600) continue;
        #pragma unroll
        for (int j = 0; j < 4; j++) {
            int n = n0 + tx * 4 + j;
            C[(size_t)m * 512 + n] = acc[i][j] + bias[n];
        }
    }
}

// =====================================================================
// 2) scores[bh][p][w] = sum_c q[bh][p][c] * k[bh][w][c]   (K=64)
// =====================================================================
__global__ void scores_kernel()
{
    __shared__ float As[16][64];
    __shared__ float Bs[16][64];

    int z = blockIdx.z;            // bh
    int b = z >> 3, h = z & 7;
    const float* A  = g_q + (size_t)b * PP * DD + h * DK;   // row stride 512
    const float* Bk = g_k + (size_t)b * PP * DD + h * DK;
    float* C = g_scores + (size_t)z * PP * PP;

    int tid = threadIdx.x;
    int m0 = blockIdx.x * 64;
    int n0 = blockIdx.y * 64;
    int tx = tid & 15, ty = tid >> 4;

    float acc[4][4] = {};
    for (int k0 = 0; k0 < 64; k0 += 16) {
        #pragma unroll
        for (int i = 0; i < 4; i++) {
            int idx = tid + i * 256;
            int r = idx >> 4, kk = idx & 15;
            As[kk][r] = (m0 + r < PP) ? A[(size_t)(m0 + r) * 512 + k0 + kk] : 0.f;
            Bs[kk][r] = (n0 + r < PP) ? Bk[(size_t)(n0 + r) * 512 + k0 + kk] : 0.f;
        }
        __syncthreads();
        #pragma unroll
        for (int kk = 0; kk < 16; kk++) {
            float a[4], b2[4];
            #pragma unroll
            for (int i = 0; i < 4; i++) a[i] = As[kk][ty * 4 + i];
            #pragma unroll
            for (int j = 0; j < 4; j++) b2[j] = Bs[kk][tx * 4 + j];
            #pragma unroll
            for (int i = 0; i < 4; i++)
                #pragma unroll
                for (int j = 0; j < 4; j++)
                    acc[i][j] += a[i] * b2[j];
        }
        __syncthreads();
    }
    #pragma unroll
    for (int i = 0; i < 4; i++) {
        int m = m0 + ty * 4 + i;
        if (m >= PP) continue;
        #pragma unroll
        for (int j = 0; j < 4; j++) {
            int n = n0 + tx * 4 + j;
            if (n < PP) C[(size_t)m * PP + n] = acc[i][j];
        }
    }
}

// =====================================================================
// 3) column argmax over rows (first-occurrence on ties, like jnp.argmax)
// =====================================================================
__global__ void argmax_kernel()
{
    int bh = blockIdx.x;
    int w = blockIdx.y * 256 + threadIdx.x;
    if (w >= PP) return;
    const float* S = g_scores + (size_t)bh * PP * PP + w;
    float best = -1e30f; int bi = 0;
    for (int r = 0; r < PP; r += 4) {
        float v0 = S[(size_t)(r + 0) * PP];
        float v1 = S[(size_t)(r + 1) * PP];
        float v2 = S[(size_t)(r + 2) * PP];
        float v3 = S[(size_t)(r + 3) * PP];
        if (v0 > best) { best = v0; bi = r; }
        if (v1 > best) { best = v1; bi = r + 1; }
        if (v2 > best) { best = v2; bi = r + 2; }
        if (v3 > best) { best = v3; bi = r + 3; }
    }
    g_idx[bh * PP + w] = bi;
}

// =====================================================================
// 4) gaussian modulation + /sqrt(dk) + row softmax, in place
// =====================================================================
__global__ void softmax_kernel()
{
    __shared__ float buf[PP];
    __shared__ float red[256];

    int row = blockIdx.x;            // 0..28799
    int bh = row / PP, p0 = row % PP;
    int t = threadIdx.x;

    float ys0 = -1.f + (2.f / 29.f) * (float)(p0 / SIDE);
    float xs0 = -1.f + (2.f / 29.f) * (float)(p0 % SIDE);

    float* S = g_scores + (size_t)bh * PP * PP + (size_t)p0 * PP;
    const int* idx = g_idx + bh * PP;

    float lmax = -1e30f;
    for (int w = t; w < PP; w += 256) {
        int id = idx[w];
        float dy = ys0 - (float)(id / SIDE);
        float dx = xs0 - (float)(id % SIDE);
        float g = __expf(-(dx * dx + dy * dy) * (1.f / 50.f));
        float v = S[w] * g * 0.125f;
        buf[w] = v;
        lmax = fmaxf(lmax, v);
    }
    red[t] = lmax; __syncthreads();
    for (int s = 128; s > 0; s >>= 1) {
        if (t < s) red[t] = fmaxf(red[t], red[t + s]);
        __syncthreads();
    }
    float m = red[0];
    __syncthreads();

    float lsum = 0.f;
    for (int w = t; w < PP; w += 256) {
        float e = __expf(buf[w] - m);
        buf[w] = e;
        lsum += e;
    }
    red[t] = lsum; __syncthreads();
    for (int s = 128; s > 0; s >>= 1) {
        if (t < s) red[t] += red[t + s];
        __syncthreads();
    }
    float inv = 1.f / red[0];
    for (int w = t; w < PP; w += 256) S[w] = buf[w] * inv;
}

// =====================================================================
// 5) conv1: 8 -> 32 channels, 3x3 SAME, relu.  Tile 64x16 px, 1x4 micro.
// =====================================================================
__global__ void conv1_kernel(const float* __restrict__ w1, const float* __restrict__ b1)
{
    __shared__ float sin_[8][18][66];
    __shared__ float sw[2304];   // [(ic*9+tap)*32 + oc]
    __shared__ float sb[32];

    int n = blockIdx.z;
    int ty0 = blockIdx.y * 16;
    int tx0 = blockIdx.x * 64;
    int tid = threadIdx.x;

    for (int i = tid; i < 2304; i += 256) {
        int ict = i >> 5, oc = i & 31;
        sw[i] = w1[oc * 72 + ict];
    }
    if (tid < 32) sb[tid] = b1[tid];

    for (int i = tid; i < 8 * 18 * 66; i += 256) {
        int ic = i / (18 * 66);
        int rem = i % (18 * 66);
        int r = rem / 66, c = rem % 66;
        int gy = ty0 - 1 + r, gx = tx0 - 1 + c;
        float v = 0.f;
        if ((unsigned)gy < PP && (unsigned)gx < PP)
            v = g_scores[((size_t)(n * 8 + ic) * PP + gy) * PP + gx];
        sin_[ic][r][c] = v;
    }
    __syncthreads();

    int tx = tid & 15, ty = tid >> 4;
    int ox = tx * 4, oy = ty;
    int gy = ty0 + oy;

    #pragma unroll
    for (int g = 0; g < 4; g++) {
        float acc[8][4];
        #pragma unroll
        for (int o = 0; o < 8; o++) {
            float bb = sb[g * 8 + o];
            acc[o][0] = bb; acc[o][1] = bb; acc[o][2] = bb; acc[o][3] = bb;
        }
        for (int ic = 0; ic < 8; ic++) {
            float pt[3][6];
            #pragma unroll
            for (int r = 0; r < 3; r++)
                #pragma unroll
                for (int c = 0; c < 6; c++)
                    pt[r][c] = sin_[ic][oy + r][ox + c];
            #pragma unroll
            for (int ky = 0; ky < 3; ky++)
                #pragma unroll
                for (int kx = 0; kx < 3; kx++) {
                    int wb = (ic * 9 + ky * 3 + kx) * 32 + g * 8;
                    #pragma unroll
                    for (int o = 0; o < 8; o++) {
                        float w = sw[wb + o];
                        #pragma unroll
                        for (int j = 0; j < 4; j++)
                            acc[o][j] += w * pt[ky][kx + j];
                    }
                }
        }
        if (gy < PP) {
            #pragma unroll
            for (int o = 0; o < 8; o++) {
                int oc = g * 8 + o;
                float* dst = g_conv1 + ((size_t)(n * C1 + oc) * PP + gy) * PP + tx0 + ox;
                #pragma unroll
                for (int j = 0; j < 4; j++) {
                    int gx = tx0 + ox + j;
                    if (gx < PP) dst[j] = fmaxf(acc[o][j], 0.f);
                }
            }
        }
    }
}

// =====================================================================
// 6) conv2: 32 -> 8 channels, 3x3 SAME, relu, fused with
//    sum_q out2[b][h][p][q]*value[b][q] -> per-tile partials
// =====================================================================
__global__ void conv2_kernel(const float* __restrict__ w2, const float* __restrict__ b2,
                             const float* __restrict__ value)
{
    __shared__ float sin_[8][18][66];
    __shared__ float sw[2304];   // [(ic*9+tap)*8 + oc]
    __shared__ float sb[8];

    int n = blockIdx.z;
    int ty0 = blockIdx.y * 16;
    int tx0 = blockIdx.x * 64;
    int tid = threadIdx.x;

    for (int i = tid; i < 2304; i += 256) {
        int ict = i >> 3, oc = i & 7;
        sw[i] = w2[oc * 288 + ict];
    }
    if (tid < 8) sb[tid] = b2[tid];

    int tx = tid & 15, ty = tid >> 4;
    int ox = tx * 4, oy = ty;
    int gy = ty0 + oy;

    float acc[8][4];
    #pragma unroll
    for (int o = 0; o < 8; o++) {
        acc[o][0] = 0.f; acc[o][1] = 0.f; acc[o][2] = 0.f; acc[o][3] = 0.f;
    }

    for (int chunk = 0; chunk < 4; chunk++) {
        __syncthreads();
        for (int i = tid; i < 8 * 18 * 66; i += 256) {
            int ic = i / (18 * 66);
            int rem = i % (18 * 66);
            int r = rem / 66, c = rem % 66;
            int gy2 = ty0 - 1 + r, gx2 = tx0 - 1 + c;
            float v = 0.f;
            if ((unsigned)gy2 < PP && (unsigned)gx2 < PP)
                v = g_conv1[((size_t)(n * C1 + chunk * 8 + ic) * PP + gy2) * PP + gx2];
            sin_[ic][r][c] = v;
        }
        __syncthreads();

        for (int ic = 0; ic < 8; ic++) {
            float pt[3][6];
            #pragma unroll
            for (int r = 0; r < 3; r++)
                #pragma unroll
                for (int c = 0; c < 6; c++)
                    pt[r][c] = sin_[ic][oy + r][ox + c];
            int icg = chunk * 8 + ic;
            #pragma unroll
            for (int ky = 0; ky < 3; ky++)
                #pragma unroll
                for (int kx = 0; kx < 3; kx++) {
                    int wb = (icg * 9 + ky * 3 + kx) * 8;
                    #pragma unroll
                    for (int o = 0; o < 8; o++) {
                        float w = sw[wb + o];
                        #pragma unroll
                        for (int j = 0; j < 4; j++)
                            acc[o][j] += w * pt[ky][kx + j];
                    }
                }
        }
    }

    // bias + relu + dot with value + sum over the 8 output channels
    float s = 0.f;
    #pragma unroll
    for (int j = 0; j < 4; j++) {
        int gx = tx0 + ox + j;
        float v = (gx < PP) ? value[n * PP + gx] : 0.f;
        float col = 0.f;
        #pragma unroll
        for (int o = 0; o < 8; o++)
            col += fmaxf(acc[o][j] + sb[o], 0.f);
        s += col * v;
    }
    if (gy >= PP) s = 0.f;

    // reduce across the 16 tx lanes of this output row (16-lane segments of the warp)
    #pragma unroll
    for (int off = 8; off > 0; off >>= 1)
        s += __shfl_down_sync(0xffffffffu, s, off, 16);

    if (tx == 0 && gy < PP)
        g_part[(n * PP + gy) * 15 + blockIdx.x] = s;
}

// =====================================================================
// 7) finalize: out[b][p] = (1/8) * sum_tiles partials
// =====================================================================
__global__ void finalize_kernel(float* __restrict__ out)
{
    int i = blockIdx.x * 256 + threadIdx.x;
    if (i >= BB * PP) return;
    float s = 0.f;
    #pragma unroll
    for (int t = 0; t < 15; t++) s += g_part[i * 15 + t];
    out[i] = s * 0.125f;
}

// =====================================================================
extern "C" void kernel_launch(void* const* d_in, const int* in_sizes, int n_in,
                              void* d_out, int out_size)
{
    const float* query = (const float*)d_in[0];
    const float* key_t = (const float*)d_in[1];
    const float* value = (const float*)d_in[2];
    const float* Wq    = (const float*)d_in[3];
    const float* bq    = (const float*)d_in[4];
    const float* Wk    = (const float*)d_in[5];
    const float* bk    = (const float*)d_in[6];
    const float* w1    = (const float*)d_in[7];
    const float* b1    = (const float*)d_in[8];
    const float* w2    = (const float*)d_in[9];
    const float* b2    = (const float*)d_in[10];

    dim3 gp(57, 8);
    proj_kernel<<<gp, 256>>>(query, Wq, bq, 0);
    proj_kernel<<<gp, 256>>>(key_t, Wk, bk, 1);

    dim3 gs(15, 15, NBH);
    scores_kernel<<<gs, 256>>>();

    dim3 ga(NBH, 4);
    argmax_kernel<<<ga, 256>>>();

    softmax_kernel<<<NBH * PP, 256>>>();

    dim3 gc(15, 57, BB);
    conv1_kernel<<<gc, 256>>>(w1, b1);
    conv2_kernel<<<gc, 256>>>(w2, b2, value);

    finalize_kernel<<<15, 256>>>((float*)d_out);
}